// round 9
// baseline (speedup 1.0000x reference)
#include <cuda_runtime.h>
#include <math.h>
#include <stdint.h>

#define UNITS     128
#define N_ITER    10
#define BXS       10
#define NTHREADS  256

// ---- blocks_kernel smem (bytes) ----
#define BUFX_BYTE  0         // 128*10*4 = 5120
#define ZBH0_BYTE  5120
#define ZBL0_BYTE  7168
#define ZBH1_BYTE  9216
#define ZBL1_BYTE  11264
#define WLS_BYTE   13312     // 32768
#define K2_SMEM_BYTES 46080

// pre-split weights (bf16 raw bits): W_in [128*784], then W1..W4 [128*128] each
#define WIN_ELEMS  (128 * 784)
#define WB_ELEMS   (128 * 128)
#define TOT_ELEMS  (WIN_ELEMS + 4 * WB_ELEMS)
__device__ unsigned short g_wh[TOT_ELEMS];
__device__ unsigned short g_wl[TOT_ELEMS];

__device__ __forceinline__ uint32_t smem_u32(const void* p) {
    uint32_t a;
    asm("{ .reg .u64 t; cvta.to.shared.u64 t, %1; cvt.u32.u64 %0, t; }" : "=r"(a) : "l"(p));
    return a;
}
__device__ __forceinline__ float fast_tanh(float x) {
    float e, r;
    asm("ex2.approx.f32 %0, %1;" : "=f"(e) : "f"(x * 2.8853900817779268f));
    asm("rcp.approx.f32 %0, %1;" : "=f"(r) : "f"(e + 1.0f));
    return fmaf(-2.0f, r, 1.0f);
}
__device__ __forceinline__ uint32_t bfpack(float lo, float hi) {
    uint32_t r;
    asm("cvt.rn.bf16x2.f32 %0, %1, %2;" : "=r"(r) : "f"(hi), "f"(lo));
    return r;
}
__device__ __forceinline__ unsigned short f2bf(float f) {
    unsigned short h;
    asm("cvt.rn.bf16.f32 %0, %1;" : "=h"(h) : "f"(f));
    return h;
}
__device__ __forceinline__ void mma_bf16(float* c,
                                         uint32_t a0, uint32_t a1, uint32_t a2, uint32_t a3,
                                         uint32_t b0, uint32_t b1) {
    asm volatile(
        "mma.sync.aligned.m16n8k16.row.col.f32.bf16.bf16.f32 "
        "{%0,%1,%2,%3}, {%4,%5,%6,%7}, {%8,%9}, {%0,%1,%2,%3};"
        : "+f"(c[0]), "+f"(c[1]), "+f"(c[2]), "+f"(c[3])
        : "r"(a0), "r"(a1), "r"(a2), "r"(a3), "r"(b0), "r"(b1));
}

extern __shared__ float smem[];

// ================== Prep: split weights into bf16 hi/lo ==================
__global__ __launch_bounds__(256, 4)
void split_kernel(const float* __restrict__ W_in,
                  const float* __restrict__ W1,
                  const float* __restrict__ W2,
                  const float* __restrict__ W3,
                  const float* __restrict__ W4)
{
    int i = blockIdx.x * 256 + threadIdx.x;
    if (i >= TOT_ELEMS) return;
    float v;
    if (i < WIN_ELEMS) {
        v = W_in[i];
    } else {
        int j = i - WIN_ELEMS;
        int b = j >> 14;
        int o = j & (WB_ELEMS - 1);
        v = (b == 0 ? W1 : b == 1 ? W2 : b == 2 ? W3 : W4)[o];
    }
    unsigned short h = f2bf(v);
    float lo = v - __uint_as_float(((uint32_t)h) << 16);
    g_wh[i] = h;
    g_wl[i] = f2bf(lo);
}

// ================== Main: phase0 + 4 implicit blocks + softmax ==================
// grid 256 CTAs x 8 rows, 256 threads (8 warps; warp = one 16-unit M-tile)
__global__ __launch_bounds__(NTHREADS, 2)
void blocks_kernel(const float* __restrict__ x,
                   const float* __restrict__ b_in,
                   const float* __restrict__ W_out,
                   const float* __restrict__ b_out,
                   float* __restrict__ out)
{
    const int tid  = threadIdx.x;
    const int row0 = blockIdx.x * 8;

    char* smem_c = (char*)smem;
    const uint32_t sbase = smem_u32(smem);
    const uint32_t sWls  = sbase + WLS_BYTE;

    float* bufX = (float*)(smem_c + BUFX_BYTE);
    float* sEpi = (float*)(smem_c + WLS_BYTE);

    const int lane = tid & 31;
    const int warp = tid >> 5;     // = M-tile index (0..7)
    const int g    = lane >> 2;
    const int t    = lane & 3;

    const int      l0 = 8 * t + (g >> 1);
    const uint32_t hb = (uint32_t)(g & 1) * 2;

    // =========== Phase 0 (fused): xf = x @ W_in^T + b_in via HMMA ===========
    // 3 independent accumulator chains to expose HMMA ILP
    float xf[4];
    {
        float p0[4], p1[4], p2[4];
        {
            int m = warp * 16 + g;
            float b0 = b_in[m], b1 = b_in[m + 8];
            p0[0] = b0;  p0[1] = b0;  p0[2] = b1;  p0[3] = b1;
            #pragma unroll
            for (int e = 0; e < 4; ++e) { p1[e] = 0.f; p2[e] = 0.f; }
        }
        const float* xp_base = x + (row0 + g) * 784 + 2 * t;
        #pragma unroll 7
        for (int kt = 0; kt < 49; ++kt) {
            const int k0 = kt * 16;
            float2 xv0 = *(const float2*)(xp_base + k0);
            float2 xv1 = *(const float2*)(xp_base + k0 + 8);
            uint32_t bh0 = bfpack(xv0.x, xv0.y);
            uint32_t bh1 = bfpack(xv1.x, xv1.y);
            float e0 = xv0.x - __uint_as_float(bh0 << 16);
            float e1 = xv0.y - __uint_as_float(bh0 & 0xFFFF0000u);
            float e2 = xv1.x - __uint_as_float(bh1 << 16);
            float e3 = xv1.y - __uint_as_float(bh1 & 0xFFFF0000u);
            uint32_t bl0 = bfpack(e0, e1);
            uint32_t bl1 = bfpack(e2, e3);
            uint32_t ah[4], al[4];
            #pragma unroll
            for (int r = 0; r < 4; ++r) {
                int m  = warp * 16 + g + ((r & 1) << 3);
                int kk = k0 + ((r >> 1) << 3) + 2 * t;
                ah[r] = *(const uint32_t*)&g_wh[m * 784 + kk];
                al[r] = *(const uint32_t*)&g_wl[m * 784 + kk];
            }
            mma_bf16(p0, ah[0], ah[1], ah[2], ah[3], bh0, bh1);
            mma_bf16(p1, ah[0], ah[1], ah[2], ah[3], bl0, bl1);
            mma_bf16(p2, al[0], al[1], al[2], al[3], bh0, bh1);
        }
        #pragma unroll
        for (int e = 0; e < 4; ++e) xf[e] = p0[e] + (p1[e] + p2[e]);
    }

    // =========== 4 implicit blocks ===========
    uint32_t wh[8][4];
    float zv[4];

    for (int blk = 0; blk < 4; ++blk) {
        const unsigned short* whb = g_wh + WIN_ELEMS + blk * WB_ELEMS;
        const unsigned short* wlb = g_wl + WIN_ELEMS + blk * WB_ELEMS;

        // ---- W fragments: Wh -> regs, Wl -> M-tile-private smem ----
        #pragma unroll
        for (int kt = 0; kt < 8; ++kt) {
            uint32_t wlv[4];
            #pragma unroll
            for (int r = 0; r < 4; ++r) {
                int m  = warp * 16 + g + ((r & 1) << 3);
                int kk = kt * 16 + ((r >> 1) << 3) + 2 * t;
                wh[kt][r] = *(const uint32_t*)&whb[m * 128 + kk];
                wlv[r]    = *(const uint32_t*)&wlb[m * 128 + kk];
            }
            uint32_t wadr = sWls + (uint32_t)(((warp * 8 + kt) * 32 + lane) * 16);
            asm volatile("st.shared.v4.b32 [%0], {%1,%2,%3,%4};"
                         :: "r"(wadr), "r"(wlv[0]), "r"(wlv[1]), "r"(wlv[2]), "r"(wlv[3])
                         : "memory");
        }

        // ---- z0 = tanh(x) -> ZB buffer 0 ----
        #pragma unroll
        for (int e = 0; e < 4; ++e) zv[e] = fast_tanh(xf[e]);

        {
            uint32_t base = (uint32_t)(warp * 256);
            #pragma unroll
            for (int e = 0; e < 4; ++e) {
                float zz = zv[e];
                unsigned short h = f2bf(zz);
                float lo = zz - __uint_as_float(((uint32_t)h) << 16);
                unsigned short l = f2bf(lo);
                uint32_t off = base + (uint32_t)(((e & 1) ? l0 + 4 : l0) * 8)
                             + (uint32_t)((e >> 1) * 4) + hb;
                asm volatile("st.shared.b16 [%0], %1;" :: "r"(sbase + ZBH0_BYTE + off), "h"(h) : "memory");
                asm volatile("st.shared.b16 [%0], %1;" :: "r"(sbase + ZBL0_BYTE + off), "h"(l) : "memory");
            }
        }
        __syncthreads();

        // ---- Picard iterations, ping-pong ZB, 1 barrier/iter ----
        for (int it = 0; it < N_ITER; ++it) {
            const uint32_t rb = (it & 1) ? 4096u : 0u;
            const uint32_t wb = (it & 1) ? 0u : 4096u;
            // 3 independent accumulator chains
            float a_hh[4], a_hl[4], a_lh[4];
            #pragma unroll
            for (int e = 0; e < 4; ++e) {
                a_hh[e] = xf[e];  a_hl[e] = 0.f;  a_lh[e] = 0.f;
            }

            #pragma unroll
            for (int kt = 0; kt < 8; ++kt) {
                uint32_t zh0, zh1, zl0, zl1;
                uint32_t off = (uint32_t)((kt * 32 + lane) * 8);
                asm volatile("ld.shared.v2.b32 {%0,%1}, [%2];"
                             : "=r"(zh0), "=r"(zh1) : "r"(sbase + ZBH0_BYTE + rb + off));
                asm volatile("ld.shared.v2.b32 {%0,%1}, [%2];"
                             : "=r"(zl0), "=r"(zl1) : "r"(sbase + ZBL0_BYTE + rb + off));
                uint32_t wl0, wl1, wl2, wl3;
                uint32_t wadr = sWls + (uint32_t)(((warp * 8 + kt) * 32 + lane) * 16);
                asm volatile("ld.shared.v4.b32 {%0,%1,%2,%3}, [%4];"
                             : "=r"(wl0), "=r"(wl1), "=r"(wl2), "=r"(wl3)
                             : "r"(wadr));
                mma_bf16(a_hh, wh[kt][0], wh[kt][1], wh[kt][2], wh[kt][3], zh0, zh1);
                mma_bf16(a_hl, wh[kt][0], wh[kt][1], wh[kt][2], wh[kt][3], zl0, zl1);
                mma_bf16(a_lh, wl0, wl1, wl2, wl3, zh0, zh1);
            }

            #pragma unroll
            for (int e = 0; e < 4; ++e)
                zv[e] = fast_tanh(a_hh[e] + (a_hl[e] + a_lh[e]));

            if (it < N_ITER - 1) {
                uint32_t base = (uint32_t)(warp * 256);
                #pragma unroll
                for (int e = 0; e < 4; ++e) {
                    float zz = zv[e];
                    unsigned short h = f2bf(zz);
                    float lo = zz - __uint_as_float(((uint32_t)h) << 16);
                    unsigned short l = f2bf(lo);
                    uint32_t off = base + (uint32_t)(((e & 1) ? l0 + 4 : l0) * 8)
                                 + (uint32_t)((e >> 1) * 4) + hb;
                    asm volatile("st.shared.b16 [%0], %1;"
                                 :: "r"(sbase + ZBH0_BYTE + wb + off), "h"(h) : "memory");
                    asm volatile("st.shared.b16 [%0], %1;"
                                 :: "r"(sbase + ZBL0_BYTE + wb + off), "h"(l) : "memory");
                }
                __syncthreads();
            }
        }

        #pragma unroll
        for (int e = 0; e < 4; ++e) xf[e] = zv[e];
        __syncthreads();   // all ZB reads done before next block's z0 store / Wl overwrite
    }

    // ---- final z -> bufX ----
    {
        int m0 = warp * 16 + g;
        int n0 = 2 * t;
        *(float2*)&bufX[m0 * BXS + n0]       = make_float2(zv[0], zv[1]);
        *(float2*)&bufX[(m0 + 8) * BXS + n0] = make_float2(zv[2], zv[3]);
    }
    __syncthreads();

    // ---- epilogue: logits + softmax (8 rows) ----
    for (int idx = tid; idx < 10 * UNITS; idx += NTHREADS) sEpi[idx] = W_out[idx];
    if (tid < 10) sEpi[1280 + tid] = b_out[tid];
    __syncthreads();
    float* slog = sEpi + 1296;   // [o][r], 80 floats
    if (tid < 80) {
        int o = tid >> 3;
        int r = tid & 7;
        float acc = sEpi[1280 + o];
        #pragma unroll 8
        for (int k = 0; k < UNITS; ++k)
            acc += bufX[k * BXS + r] * sEpi[o * UNITS + k];
        slog[o * 8 + r] = acc;
    }
    __syncthreads();
    if (tid < 8) {
        int r = tid;
        float l[10];
        float m = -INFINITY;
        #pragma unroll
        for (int o = 0; o < 10; ++o) { l[o] = slog[o * 8 + r]; m = fmaxf(m, l[o]); }
        float s = 0.f;
        #pragma unroll
        for (int o = 0; o < 10; ++o) { l[o] = expf(l[o] - m); s += l[o]; }
        float inv = 1.f / s;
        #pragma unroll
        for (int o = 0; o < 10; ++o) out[(row0 + r) * 10 + o] = l[o] * inv;
    }
}

extern "C" void kernel_launch(void* const* d_in, const int* in_sizes, int n_in,
                              void* d_out, int out_size)
{
    const float* x     = (const float*)d_in[0];
    const float* W_in  = (const float*)d_in[1];
    const float* b_in  = (const float*)d_in[2];
    const float* W1    = (const float*)d_in[3];
    const float* W2    = (const float*)d_in[4];
    const float* W3    = (const float*)d_in[5];
    const float* W4    = (const float*)d_in[6];
    const float* W_out = (const float*)d_in[7];
    const float* b_out = (const float*)d_in[8];
    float* out = (float*)d_out;

    cudaFuncSetAttribute(blocks_kernel,
                         cudaFuncAttributeMaxDynamicSharedMemorySize, K2_SMEM_BYTES);

    split_kernel<<<(TOT_ELEMS + 255) / 256, 256>>>(W_in, W1, W2, W3, W4);
    blocks_kernel<<<256, NTHREADS, K2_SMEM_BYTES>>>(x, b_in, W_out, b_out, out);
}

// round 10
// speedup vs baseline: 1.1926x; 1.1926x over previous
#include <cuda_runtime.h>
#include <math.h>
#include <stdint.h>

#define UNITS     128
#define N_ITER    8
#define N_CHEAP   4      // iterations 0..N_CHEAP-1 use Wh*zh only
#define BXS       10
#define NTHREADS  256

// ---- blocks_kernel smem (bytes) ----
#define BUFX_BYTE  0         // 128*10*4 = 5120
#define ZBH0_BYTE  5120
#define ZBL0_BYTE  7168
#define ZBH1_BYTE  9216
#define ZBL1_BYTE  11264
#define WLS_BYTE   13312     // 32768
#define K2_SMEM_BYTES 46080

// pre-split weights (bf16 raw bits): W_in [128*784], then W1..W4 [128*128] each
#define WIN_ELEMS  (128 * 784)
#define WB_ELEMS   (128 * 128)
#define TOT_ELEMS  (WIN_ELEMS + 4 * WB_ELEMS)
__device__ unsigned short g_wh[TOT_ELEMS];
__device__ unsigned short g_wl[TOT_ELEMS];

__device__ __forceinline__ uint32_t smem_u32(const void* p) {
    uint32_t a;
    asm("{ .reg .u64 t; cvta.to.shared.u64 t, %1; cvt.u32.u64 %0, t; }" : "=r"(a) : "l"(p));
    return a;
}
__device__ __forceinline__ float fast_tanh(float x) {
    float e, r;
    asm("ex2.approx.f32 %0, %1;" : "=f"(e) : "f"(x * 2.8853900817779268f));
    asm("rcp.approx.f32 %0, %1;" : "=f"(r) : "f"(e + 1.0f));
    return fmaf(-2.0f, r, 1.0f);
}
__device__ __forceinline__ uint32_t bfpack(float lo, float hi) {
    uint32_t r;
    asm("cvt.rn.bf16x2.f32 %0, %1, %2;" : "=r"(r) : "f"(hi), "f"(lo));
    return r;
}
__device__ __forceinline__ unsigned short f2bf(float f) {
    unsigned short h;
    asm("cvt.rn.bf16.f32 %0, %1;" : "=h"(h) : "f"(f));
    return h;
}
__device__ __forceinline__ void mma_bf16(float* c,
                                         uint32_t a0, uint32_t a1, uint32_t a2, uint32_t a3,
                                         uint32_t b0, uint32_t b1) {
    asm volatile(
        "mma.sync.aligned.m16n8k16.row.col.f32.bf16.bf16.f32 "
        "{%0,%1,%2,%3}, {%4,%5,%6,%7}, {%8,%9}, {%0,%1,%2,%3};"
        : "+f"(c[0]), "+f"(c[1]), "+f"(c[2]), "+f"(c[3])
        : "r"(a0), "r"(a1), "r"(a2), "r"(a3), "r"(b0), "r"(b1));
}

extern __shared__ float smem[];

// ================== Prep: split weights into bf16 hi/lo ==================
__global__ __launch_bounds__(256, 4)
void split_kernel(const float* __restrict__ W_in,
                  const float* __restrict__ W1,
                  const float* __restrict__ W2,
                  const float* __restrict__ W3,
                  const float* __restrict__ W4)
{
    int i = blockIdx.x * 256 + threadIdx.x;
    if (i >= TOT_ELEMS) return;
    float v;
    if (i < WIN_ELEMS) {
        v = W_in[i];
    } else {
        int j = i - WIN_ELEMS;
        int b = j >> 14;
        int o = j & (WB_ELEMS - 1);
        v = (b == 0 ? W1 : b == 1 ? W2 : b == 2 ? W3 : W4)[o];
    }
    unsigned short h = f2bf(v);
    float lo = v - __uint_as_float(((uint32_t)h) << 16);
    g_wh[i] = h;
    g_wl[i] = f2bf(lo);
}

// ================== Main: phase0 + 4 implicit blocks + softmax ==================
// grid 256 CTAs x 8 rows, 256 threads (8 warps; warp = one 16-unit M-tile)
__global__ __launch_bounds__(NTHREADS, 2)
void blocks_kernel(const float* __restrict__ x,
                   const float* __restrict__ b_in,
                   const float* __restrict__ W_out,
                   const float* __restrict__ b_out,
                   float* __restrict__ out)
{
    const int tid  = threadIdx.x;
    const int row0 = blockIdx.x * 8;

    char* smem_c = (char*)smem;
    const uint32_t sbase = smem_u32(smem);
    const uint32_t sWls  = sbase + WLS_BYTE;

    float* bufX = (float*)(smem_c + BUFX_BYTE);
    float* sEpi = (float*)(smem_c + WLS_BYTE);

    const int lane = tid & 31;
    const int warp = tid >> 5;     // = M-tile index (0..7)
    const int g    = lane >> 2;
    const int t    = lane & 3;

    const int      l0 = 8 * t + (g >> 1);
    const uint32_t hb = (uint32_t)(g & 1) * 2;

    // =========== Phase 0 (fused): xf = x @ W_in^T + b_in via HMMA ===========
    float xf[4];
    {
        float p0[4], p1[4], p2[4];
        {
            int m = warp * 16 + g;
            float b0 = b_in[m], b1 = b_in[m + 8];
            p0[0] = b0;  p0[1] = b0;  p0[2] = b1;  p0[3] = b1;
            #pragma unroll
            for (int e = 0; e < 4; ++e) { p1[e] = 0.f; p2[e] = 0.f; }
        }
        const float* xp_base = x + (row0 + g) * 784 + 2 * t;
        #pragma unroll 7
        for (int kt = 0; kt < 49; ++kt) {
            const int k0 = kt * 16;
            float2 xv0 = *(const float2*)(xp_base + k0);
            float2 xv1 = *(const float2*)(xp_base + k0 + 8);
            uint32_t bh0 = bfpack(xv0.x, xv0.y);
            uint32_t bh1 = bfpack(xv1.x, xv1.y);
            float e0 = xv0.x - __uint_as_float(bh0 << 16);
            float e1 = xv0.y - __uint_as_float(bh0 & 0xFFFF0000u);
            float e2 = xv1.x - __uint_as_float(bh1 << 16);
            float e3 = xv1.y - __uint_as_float(bh1 & 0xFFFF0000u);
            uint32_t bl0 = bfpack(e0, e1);
            uint32_t bl1 = bfpack(e2, e3);
            uint32_t ah[4], al[4];
            #pragma unroll
            for (int r = 0; r < 4; ++r) {
                int m  = warp * 16 + g + ((r & 1) << 3);
                int kk = k0 + ((r >> 1) << 3) + 2 * t;
                ah[r] = *(const uint32_t*)&g_wh[m * 784 + kk];
                al[r] = *(const uint32_t*)&g_wl[m * 784 + kk];
            }
            mma_bf16(p0, ah[0], ah[1], ah[2], ah[3], bh0, bh1);
            mma_bf16(p1, ah[0], ah[1], ah[2], ah[3], bl0, bl1);
            mma_bf16(p2, al[0], al[1], al[2], al[3], bh0, bh1);
        }
        #pragma unroll
        for (int e = 0; e < 4; ++e) xf[e] = p0[e] + (p1[e] + p2[e]);
    }

    // =========== 4 implicit blocks ===========
    uint32_t wh[8][4];
    float zv[4];

    for (int blk = 0; blk < 4; ++blk) {
        const unsigned short* whb = g_wh + WIN_ELEMS + blk * WB_ELEMS;
        const unsigned short* wlb = g_wl + WIN_ELEMS + blk * WB_ELEMS;

        // ---- W fragments: Wh -> regs, Wl -> M-tile-private smem ----
        #pragma unroll
        for (int kt = 0; kt < 8; ++kt) {
            uint32_t wlv[4];
            #pragma unroll
            for (int r = 0; r < 4; ++r) {
                int m  = warp * 16 + g + ((r & 1) << 3);
                int kk = kt * 16 + ((r >> 1) << 3) + 2 * t;
                wh[kt][r] = *(const uint32_t*)&whb[m * 128 + kk];
                wlv[r]    = *(const uint32_t*)&wlb[m * 128 + kk];
            }
            uint32_t wadr = sWls + (uint32_t)(((warp * 8 + kt) * 32 + lane) * 16);
            asm volatile("st.shared.v4.b32 [%0], {%1,%2,%3,%4};"
                         :: "r"(wadr), "r"(wlv[0]), "r"(wlv[1]), "r"(wlv[2]), "r"(wlv[3])
                         : "memory");
        }

        // ---- z0 = tanh(x) -> ZB buffer 0 (hi only; first iteration is cheap) ----
        #pragma unroll
        for (int e = 0; e < 4; ++e) zv[e] = fast_tanh(xf[e]);

        {
            uint32_t base = (uint32_t)(warp * 256);
            #pragma unroll
            for (int e = 0; e < 4; ++e) {
                unsigned short h = f2bf(zv[e]);
                uint32_t off = base + (uint32_t)(((e & 1) ? l0 + 4 : l0) * 8)
                             + (uint32_t)((e >> 1) * 4) + hb;
                asm volatile("st.shared.b16 [%0], %1;" :: "r"(sbase + ZBH0_BYTE + off), "h"(h) : "memory");
            }
        }
        __syncthreads();

        // ---- Picard iterations: cheap (Wh*zh) then full (3-term), ping-pong ZB ----
        for (int it = 0; it < N_ITER; ++it) {
            const bool cheap = (it < N_CHEAP);
            const uint32_t rb = (it & 1) ? 4096u : 0u;
            const uint32_t wb = (it & 1) ? 0u : 4096u;
            float a_hh[4], a_hl[4], a_lh[4];
            #pragma unroll
            for (int e = 0; e < 4; ++e) {
                a_hh[e] = xf[e];  a_hl[e] = 0.f;  a_lh[e] = 0.f;
            }

            if (cheap) {
                #pragma unroll
                for (int kt = 0; kt < 8; ++kt) {
                    uint32_t zh0, zh1;
                    uint32_t off = (uint32_t)((kt * 32 + lane) * 8);
                    asm volatile("ld.shared.v2.b32 {%0,%1}, [%2];"
                                 : "=r"(zh0), "=r"(zh1) : "r"(sbase + ZBH0_BYTE + rb + off));
                    mma_bf16(a_hh, wh[kt][0], wh[kt][1], wh[kt][2], wh[kt][3], zh0, zh1);
                }
                #pragma unroll
                for (int e = 0; e < 4; ++e) zv[e] = fast_tanh(a_hh[e]);
            } else {
                #pragma unroll
                for (int kt = 0; kt < 8; ++kt) {
                    uint32_t zh0, zh1, zl0, zl1;
                    uint32_t off = (uint32_t)((kt * 32 + lane) * 8);
                    asm volatile("ld.shared.v2.b32 {%0,%1}, [%2];"
                                 : "=r"(zh0), "=r"(zh1) : "r"(sbase + ZBH0_BYTE + rb + off));
                    asm volatile("ld.shared.v2.b32 {%0,%1}, [%2];"
                                 : "=r"(zl0), "=r"(zl1) : "r"(sbase + ZBL0_BYTE + rb + off));
                    uint32_t wl0, wl1, wl2, wl3;
                    uint32_t wadr = sWls + (uint32_t)(((warp * 8 + kt) * 32 + lane) * 16);
                    asm volatile("ld.shared.v4.b32 {%0,%1,%2,%3}, [%4];"
                                 : "=r"(wl0), "=r"(wl1), "=r"(wl2), "=r"(wl3)
                                 : "r"(wadr));
                    mma_bf16(a_hh, wh[kt][0], wh[kt][1], wh[kt][2], wh[kt][3], zh0, zh1);
                    mma_bf16(a_hl, wh[kt][0], wh[kt][1], wh[kt][2], wh[kt][3], zl0, zl1);
                    mma_bf16(a_lh, wl0, wl1, wl2, wl3, zh0, zh1);
                }
                #pragma unroll
                for (int e = 0; e < 4; ++e)
                    zv[e] = fast_tanh(a_hh[e] + (a_hl[e] + a_lh[e]));
            }

            if (it < N_ITER - 1) {
                const bool need_lo = (it >= N_CHEAP - 1);   // next iter is full
                uint32_t base = (uint32_t)(warp * 256);
                #pragma unroll
                for (int e = 0; e < 4; ++e) {
                    float zz = zv[e];
                    unsigned short h = f2bf(zz);
                    uint32_t off = base + (uint32_t)(((e & 1) ? l0 + 4 : l0) * 8)
                                 + (uint32_t)((e >> 1) * 4) + hb;
                    asm volatile("st.shared.b16 [%0], %1;"
                                 :: "r"(sbase + ZBH0_BYTE + wb + off), "h"(h) : "memory");
                    if (need_lo) {
                        float lo = zz - __uint_as_float(((uint32_t)h) << 16);
                        unsigned short l = f2bf(lo);
                        asm volatile("st.shared.b16 [%0], %1;"
                                     :: "r"(sbase + ZBL0_BYTE + wb + off), "h"(l) : "memory");
                    }
                }
                __syncthreads();
            }
        }

        #pragma unroll
        for (int e = 0; e < 4; ++e) xf[e] = zv[e];
        __syncthreads();   // all ZB reads done before next block's z0 store / Wl overwrite
    }

    // ---- final z -> bufX ----
    {
        int m0 = warp * 16 + g;
        int n0 = 2 * t;
        *(float2*)&bufX[m0 * BXS + n0]       = make_float2(zv[0], zv[1]);
        *(float2*)&bufX[(m0 + 8) * BXS + n0] = make_float2(zv[2], zv[3]);
    }
    __syncthreads();

    // ---- epilogue: logits + softmax (8 rows) ----
    for (int idx = tid; idx < 10 * UNITS; idx += NTHREADS) sEpi[idx] = W_out[idx];
    if (tid < 10) sEpi[1280 + tid] = b_out[tid];
    __syncthreads();
    float* slog = sEpi + 1296;   // [o][r], 80 floats
    if (tid < 80) {
        int o = tid >> 3;
        int r = tid & 7;
        float acc = sEpi[1280 + o];
        #pragma unroll 8
        for (int k = 0; k < UNITS; ++k)
            acc += bufX[k * BXS + r] * sEpi[o * UNITS + k];
        slog[o * 8 + r] = acc;
    }
    __syncthreads();
    if (tid < 8) {
        int r = tid;
        float l[10];
        float m = -INFINITY;
        #pragma unroll
        for (int o = 0; o < 10; ++o) { l[o] = slog[o * 8 + r]; m = fmaxf(m, l[o]); }
        float s = 0.f;
        #pragma unroll
        for (int o = 0; o < 10; ++o) { l[o] = expf(l[o] - m); s += l[o]; }
        float inv = 1.f / s;
        #pragma unroll
        for (int o = 0; o < 10; ++o) out[(row0 + r) * 10 + o] = l[o] * inv;
    }
}

extern "C" void kernel_launch(void* const* d_in, const int* in_sizes, int n_in,
                              void* d_out, int out_size)
{
    const float* x     = (const float*)d_in[0];
    const float* W_in  = (const float*)d_in[1];
    const float* b_in  = (const float*)d_in[2];
    const float* W1    = (const float*)d_in[3];
    const float* W2    = (const float*)d_in[4];
    const float* W3    = (const float*)d_in[5];
    const float* W4    = (const float*)d_in[6];
    const float* W_out = (const float*)d_in[7];
    const float* b_out = (const float*)d_in[8];
    float* out = (float*)d_out;

    cudaFuncSetAttribute(blocks_kernel,
                         cudaFuncAttributeMaxDynamicSharedMemorySize, K2_SMEM_BYTES);

    split_kernel<<<(TOT_ELEMS + 255) / 256, 256>>>(W_in, W1, W2, W3, W4);
    blocks_kernel<<<256, NTHREADS, K2_SMEM_BYTES>>>(x, b_in, W_out, b_out, out);
}

// round 11
// speedup vs baseline: 1.2681x; 1.0633x over previous
#include <cuda_runtime.h>
#include <math.h>
#include <stdint.h>

#define UNITS     128
#define N_ITER    8
#define N_CHEAP   6      // iterations 0..N_CHEAP-1 use Wh*zh only (fp16 single-term)
#define BXS       10
#define NTHREADS  256

// ---- blocks_kernel smem (bytes) ----
#define BUFX_BYTE  0         // 128*10*4 = 5120
#define ZBH0_BYTE  5120
#define ZBL0_BYTE  7168
#define ZBH1_BYTE  9216
#define ZBL1_BYTE  11264
#define WLS_BYTE   13312     // 32768
#define K2_SMEM_BYTES 46080

// pre-split weights (fp16 raw bits): W_in [128*784], then W1..W4 [128*128] each
#define WIN_ELEMS  (128 * 784)
#define WB_ELEMS   (128 * 128)
#define TOT_ELEMS  (WIN_ELEMS + 4 * WB_ELEMS)
__device__ unsigned short g_wh[TOT_ELEMS];
__device__ unsigned short g_wl[TOT_ELEMS];

__device__ __forceinline__ uint32_t smem_u32(const void* p) {
    uint32_t a;
    asm("{ .reg .u64 t; cvta.to.shared.u64 t, %1; cvt.u32.u64 %0, t; }" : "=r"(a) : "l"(p));
    return a;
}
__device__ __forceinline__ float fast_tanh(float x) {
    float e, r;
    asm("ex2.approx.f32 %0, %1;" : "=f"(e) : "f"(x * 2.8853900817779268f));
    asm("rcp.approx.f32 %0, %1;" : "=f"(r) : "f"(e + 1.0f));
    return fmaf(-2.0f, r, 1.0f);
}
// pack two f32 -> fp16x2 word {f16(hi)<<16 | f16(lo)}
__device__ __forceinline__ uint32_t hpack(float lo, float hi) {
    uint32_t r;
    asm("cvt.rn.f16x2.f32 %0, %1, %2;" : "=r"(r) : "f"(hi), "f"(lo));
    return r;
}
__device__ __forceinline__ float2 hunpack(uint32_t p) {
    float2 f;
    asm("{ .reg .b16 l, h; mov.b32 {l, h}, %2; cvt.f32.f16 %0, l; cvt.f32.f16 %1, h; }"
        : "=f"(f.x), "=f"(f.y) : "r"(p));
    return f;
}
__device__ __forceinline__ unsigned short f2h(float f) {
    unsigned short h;
    asm("cvt.rn.f16.f32 %0, %1;" : "=h"(h) : "f"(f));
    return h;
}
__device__ __forceinline__ float h2f(unsigned short h) {
    float f;
    asm("cvt.f32.f16 %0, %1;" : "=f"(f) : "h"(h));
    return f;
}
__device__ __forceinline__ void mma_f16(float* c,
                                        uint32_t a0, uint32_t a1, uint32_t a2, uint32_t a3,
                                        uint32_t b0, uint32_t b1) {
    asm volatile(
        "mma.sync.aligned.m16n8k16.row.col.f32.f16.f16.f32 "
        "{%0,%1,%2,%3}, {%4,%5,%6,%7}, {%8,%9}, {%0,%1,%2,%3};"
        : "+f"(c[0]), "+f"(c[1]), "+f"(c[2]), "+f"(c[3])
        : "r"(a0), "r"(a1), "r"(a2), "r"(a3), "r"(b0), "r"(b1));
}

extern __shared__ float smem[];

// ================== Prep: split weights into fp16 hi/lo ==================
__global__ __launch_bounds__(256, 4)
void split_kernel(const float* __restrict__ W_in,
                  const float* __restrict__ W1,
                  const float* __restrict__ W2,
                  const float* __restrict__ W3,
                  const float* __restrict__ W4)
{
    int i = blockIdx.x * 256 + threadIdx.x;
    if (i >= TOT_ELEMS) return;
    float v;
    if (i < WIN_ELEMS) {
        v = W_in[i];
    } else {
        int j = i - WIN_ELEMS;
        int b = j >> 14;
        int o = j & (WB_ELEMS - 1);
        v = (b == 0 ? W1 : b == 1 ? W2 : b == 2 ? W3 : W4)[o];
    }
    unsigned short h = f2h(v);
    float lo = v - h2f(h);
    g_wh[i] = h;
    g_wl[i] = f2h(lo);
}

// ================== Main: phase0 + 4 implicit blocks + softmax ==================
// grid 256 CTAs x 8 rows, 256 threads (8 warps; warp = one 16-unit M-tile)
__global__ __launch_bounds__(NTHREADS, 2)
void blocks_kernel(const float* __restrict__ x,
                   const float* __restrict__ b_in,
                   const float* __restrict__ W_out,
                   const float* __restrict__ b_out,
                   float* __restrict__ out)
{
    const int tid  = threadIdx.x;
    const int row0 = blockIdx.x * 8;

    char* smem_c = (char*)smem;
    const uint32_t sbase = smem_u32(smem);
    const uint32_t sWls  = sbase + WLS_BYTE;

    float* bufX = (float*)(smem_c + BUFX_BYTE);
    float* sEpi = (float*)(smem_c + WLS_BYTE);

    const int lane = tid & 31;
    const int warp = tid >> 5;     // = M-tile index (0..7)
    const int g    = lane >> 2;
    const int t    = lane & 3;

    const int      l0 = 8 * t + (g >> 1);
    const uint32_t hb = (uint32_t)(g & 1) * 2;

    // =========== Phase 0 (fused): xf = x @ W_in^T + b_in via HMMA (fp16 3-term) ===========
    float xf[4];
    {
        float p0[4], p1[4], p2[4];
        {
            int m = warp * 16 + g;
            float b0 = b_in[m], b1 = b_in[m + 8];
            p0[0] = b0;  p0[1] = b0;  p0[2] = b1;  p0[3] = b1;
            #pragma unroll
            for (int e = 0; e < 4; ++e) { p1[e] = 0.f; p2[e] = 0.f; }
        }
        const float* xp_base = x + (row0 + g) * 784 + 2 * t;
        #pragma unroll 7
        for (int kt = 0; kt < 49; ++kt) {
            const int k0 = kt * 16;
            float2 xv0 = *(const float2*)(xp_base + k0);
            float2 xv1 = *(const float2*)(xp_base + k0 + 8);
            uint32_t bh0 = hpack(xv0.x, xv0.y);
            uint32_t bh1 = hpack(xv1.x, xv1.y);
            float2 r0 = hunpack(bh0);
            float2 r1 = hunpack(bh1);
            uint32_t bl0 = hpack(xv0.x - r0.x, xv0.y - r0.y);
            uint32_t bl1 = hpack(xv1.x - r1.x, xv1.y - r1.y);
            uint32_t ah[4], al[4];
            #pragma unroll
            for (int r = 0; r < 4; ++r) {
                int m  = warp * 16 + g + ((r & 1) << 3);
                int kk = k0 + ((r >> 1) << 3) + 2 * t;
                ah[r] = *(const uint32_t*)&g_wh[m * 784 + kk];
                al[r] = *(const uint32_t*)&g_wl[m * 784 + kk];
            }
            mma_f16(p0, ah[0], ah[1], ah[2], ah[3], bh0, bh1);
            mma_f16(p1, ah[0], ah[1], ah[2], ah[3], bl0, bl1);
            mma_f16(p2, al[0], al[1], al[2], al[3], bh0, bh1);
        }
        #pragma unroll
        for (int e = 0; e < 4; ++e) xf[e] = p0[e] + (p1[e] + p2[e]);
    }

    // =========== 4 implicit blocks ===========
    uint32_t wh[8][4];
    float zv[4];

    for (int blk = 0; blk < 4; ++blk) {
        const unsigned short* whb = g_wh + WIN_ELEMS + blk * WB_ELEMS;
        const unsigned short* wlb = g_wl + WIN_ELEMS + blk * WB_ELEMS;

        // ---- W fragments: Wh -> regs, Wl -> M-tile-private smem ----
        #pragma unroll
        for (int kt = 0; kt < 8; ++kt) {
            uint32_t wlv[4];
            #pragma unroll
            for (int r = 0; r < 4; ++r) {
                int m  = warp * 16 + g + ((r & 1) << 3);
                int kk = kt * 16 + ((r >> 1) << 3) + 2 * t;
                wh[kt][r] = *(const uint32_t*)&whb[m * 128 + kk];
                wlv[r]    = *(const uint32_t*)&wlb[m * 128 + kk];
            }
            uint32_t wadr = sWls + (uint32_t)(((warp * 8 + kt) * 32 + lane) * 16);
            asm volatile("st.shared.v4.b32 [%0], {%1,%2,%3,%4};"
                         :: "r"(wadr), "r"(wlv[0]), "r"(wlv[1]), "r"(wlv[2]), "r"(wlv[3])
                         : "memory");
        }

        // ---- z0 = tanh(x) -> ZB buffer 0 (hi only; first iterations are cheap) ----
        #pragma unroll
        for (int e = 0; e < 4; ++e) zv[e] = fast_tanh(xf[e]);

        {
            uint32_t base = (uint32_t)(warp * 256);
            #pragma unroll
            for (int e = 0; e < 4; ++e) {
                unsigned short h = f2h(zv[e]);
                uint32_t off = base + (uint32_t)(((e & 1) ? l0 + 4 : l0) * 8)
                             + (uint32_t)((e >> 1) * 4) + hb;
                asm volatile("st.shared.b16 [%0], %1;" :: "r"(sbase + ZBH0_BYTE + off), "h"(h) : "memory");
            }
        }
        __syncthreads();

        // ---- Picard iterations: cheap (Wh*zh) then full (3-term), ping-pong ZB ----
        for (int it = 0; it < N_ITER; ++it) {
            const bool cheap = (it < N_CHEAP);
            const uint32_t rb = (it & 1) ? 4096u : 0u;
            const uint32_t wb = (it & 1) ? 0u : 4096u;
            float a_hh[4], a_hl[4], a_lh[4];
            #pragma unroll
            for (int e = 0; e < 4; ++e) {
                a_hh[e] = xf[e];  a_hl[e] = 0.f;  a_lh[e] = 0.f;
            }

            if (cheap) {
                #pragma unroll
                for (int kt = 0; kt < 8; ++kt) {
                    uint32_t zh0, zh1;
                    uint32_t off = (uint32_t)((kt * 32 + lane) * 8);
                    asm volatile("ld.shared.v2.b32 {%0,%1}, [%2];"
                                 : "=r"(zh0), "=r"(zh1) : "r"(sbase + ZBH0_BYTE + rb + off));
                    mma_f16(a_hh, wh[kt][0], wh[kt][1], wh[kt][2], wh[kt][3], zh0, zh1);
                }
                #pragma unroll
                for (int e = 0; e < 4; ++e) zv[e] = fast_tanh(a_hh[e]);
            } else {
                #pragma unroll
                for (int kt = 0; kt < 8; ++kt) {
                    uint32_t zh0, zh1, zl0, zl1;
                    uint32_t off = (uint32_t)((kt * 32 + lane) * 8);
                    asm volatile("ld.shared.v2.b32 {%0,%1}, [%2];"
                                 : "=r"(zh0), "=r"(zh1) : "r"(sbase + ZBH0_BYTE + rb + off));
                    asm volatile("ld.shared.v2.b32 {%0,%1}, [%2];"
                                 : "=r"(zl0), "=r"(zl1) : "r"(sbase + ZBL0_BYTE + rb + off));
                    uint32_t wl0, wl1, wl2, wl3;
                    uint32_t wadr = sWls + (uint32_t)(((warp * 8 + kt) * 32 + lane) * 16);
                    asm volatile("ld.shared.v4.b32 {%0,%1,%2,%3}, [%4];"
                                 : "=r"(wl0), "=r"(wl1), "=r"(wl2), "=r"(wl3)
                                 : "r"(wadr));
                    mma_f16(a_hh, wh[kt][0], wh[kt][1], wh[kt][2], wh[kt][3], zh0, zh1);
                    mma_f16(a_hl, wh[kt][0], wh[kt][1], wh[kt][2], wh[kt][3], zl0, zl1);
                    mma_f16(a_lh, wl0, wl1, wl2, wl3, zh0, zh1);
                }
                #pragma unroll
                for (int e = 0; e < 4; ++e)
                    zv[e] = fast_tanh(a_hh[e] + (a_hl[e] + a_lh[e]));
            }

            if (it < N_ITER - 1) {
                const bool need_lo = (it >= N_CHEAP - 1);   // next iter is full
                uint32_t base = (uint32_t)(warp * 256);
                #pragma unroll
                for (int e = 0; e < 4; ++e) {
                    float zz = zv[e];
                    unsigned short h = f2h(zz);
                    uint32_t off = base + (uint32_t)(((e & 1) ? l0 + 4 : l0) * 8)
                                 + (uint32_t)((e >> 1) * 4) + hb;
                    asm volatile("st.shared.b16 [%0], %1;"
                                 :: "r"(sbase + ZBH0_BYTE + wb + off), "h"(h) : "memory");
                    if (need_lo) {
                        unsigned short l = f2h(zz - h2f(h));
                        asm volatile("st.shared.b16 [%0], %1;"
                                     :: "r"(sbase + ZBL0_BYTE + wb + off), "h"(l) : "memory");
                    }
                }
                __syncthreads();
            }
        }

        #pragma unroll
        for (int e = 0; e < 4; ++e) xf[e] = zv[e];
        __syncthreads();   // all ZB reads done before next block's z0 store / Wl overwrite
    }

    // ---- final z -> bufX ----
    {
        int m0 = warp * 16 + g;
        int n0 = 2 * t;
        *(float2*)&bufX[m0 * BXS + n0]       = make_float2(zv[0], zv[1]);
        *(float2*)&bufX[(m0 + 8) * BXS + n0] = make_float2(zv[2], zv[3]);
    }
    __syncthreads();

    // ---- epilogue: logits + softmax (8 rows) ----
    for (int idx = tid; idx < 10 * UNITS; idx += NTHREADS) sEpi[idx] = W_out[idx];
    if (tid < 10) sEpi[1280 + tid] = b_out[tid];
    __syncthreads();
    float* slog = sEpi + 1296;   // [o][r], 80 floats
    if (tid < 80) {
        int o = tid >> 3;
        int r = tid & 7;
        float acc = sEpi[1280 + o];
        #pragma unroll 8
        for (int k = 0; k < UNITS; ++k)
            acc += bufX[k * BXS + r] * sEpi[o * UNITS + k];
        slog[o * 8 + r] = acc;
    }
    __syncthreads();
    if (tid < 8) {
        int r = tid;
        float l[10];
        float m = -INFINITY;
        #pragma unroll
        for (int o = 0; o < 10; ++o) { l[o] = slog[o * 8 + r]; m = fmaxf(m, l[o]); }
        float s = 0.f;
        #pragma unroll
        for (int o = 0; o < 10; ++o) { l[o] = expf(l[o] - m); s += l[o]; }
        float inv = 1.f / s;
        #pragma unroll
        for (int o = 0; o < 10; ++o) out[(row0 + r) * 10 + o] = l[o] * inv;
    }
}

extern "C" void kernel_launch(void* const* d_in, const int* in_sizes, int n_in,
                              void* d_out, int out_size)
{
    const float* x     = (const float*)d_in[0];
    const float* W_in  = (const float*)d_in[1];
    const float* b_in  = (const float*)d_in[2];
    const float* W1    = (const float*)d_in[3];
    const float* W2    = (const float*)d_in[4];
    const float* W3    = (const float*)d_in[5];
    const float* W4    = (const float*)d_in[6];
    const float* W_out = (const float*)d_in[7];
    const float* b_out = (const float*)d_in[8];
    float* out = (float*)d_out;

    cudaFuncSetAttribute(blocks_kernel,
                         cudaFuncAttributeMaxDynamicSharedMemorySize, K2_SMEM_BYTES);

    split_kernel<<<(TOT_ELEMS + 255) / 256, 256>>>(W_in, W1, W2, W3, W4);
    blocks_kernel<<<256, NTHREADS, K2_SMEM_BYTES>>>(x, b_in, W_out, b_out, out);
}

// round 12
// speedup vs baseline: 2.1555x; 1.6998x over previous
#include <cuda_runtime.h>
#include <math.h>
#include <stdint.h>

#define UNITS     128
#define N_ITER    8
#define N_CHEAP   6      // iterations 0..N_CHEAP-1 use Wh*zh only
#define BXS       10
#define NTHREADS  256

// ---- blocks_kernel smem (bytes) ----
#define BUFX_BYTE  0         // 128*10*4 = 5120
#define ZBH0_BYTE  5120
#define ZBL0_BYTE  7168
#define ZBH1_BYTE  9216
#define ZBL1_BYTE  11264
#define EPI_BYTE   13312     // 1376 floats = 5504 B
#define K2_SMEM_BYTES 18816

// fragment-ordered fp16 weights, 32-bit words:
// W_in: [mt(8)][kt(49)][lane(32)][r(4)] = 50176 words
// W1..4: [blk(4)][mt(8)][kt(8)][lane(32)][r(4)] = 4*8192 words
#define WIN_WORDS  50176
#define WBLK_WORDS 8192
#define TOT_WORDS  (WIN_WORDS + 4 * WBLK_WORDS)
#define BLK0_U4    (WIN_WORDS / 4)
__device__ uint32_t g_whw[TOT_WORDS];
__device__ uint32_t g_wlw[TOT_WORDS];

__device__ __forceinline__ uint32_t smem_u32(const void* p) {
    uint32_t a;
    asm("{ .reg .u64 t; cvta.to.shared.u64 t, %1; cvt.u32.u64 %0, t; }" : "=r"(a) : "l"(p));
    return a;
}
__device__ __forceinline__ float fast_tanh(float x) {
    float e, r;
    asm("ex2.approx.f32 %0, %1;" : "=f"(e) : "f"(x * 2.8853900817779268f));
    asm("rcp.approx.f32 %0, %1;" : "=f"(r) : "f"(e + 1.0f));
    return fmaf(-2.0f, r, 1.0f);
}
// pack two f32 -> fp16x2 word {f16(hi)<<16 | f16(lo)}
__device__ __forceinline__ uint32_t hpack(float lo, float hi) {
    uint32_t r;
    asm("cvt.rn.f16x2.f32 %0, %1, %2;" : "=r"(r) : "f"(hi), "f"(lo));
    return r;
}
__device__ __forceinline__ float2 hunpack(uint32_t p) {
    float2 f;
    asm("{ .reg .b16 l, h; mov.b32 {l, h}, %2; cvt.f32.f16 %0, l; cvt.f32.f16 %1, h; }"
        : "=f"(f.x), "=f"(f.y) : "r"(p));
    return f;
}
__device__ __forceinline__ unsigned short f2h(float f) {
    unsigned short h;
    asm("cvt.rn.f16.f32 %0, %1;" : "=h"(h) : "f"(f));
    return h;
}
__device__ __forceinline__ float h2f(unsigned short h) {
    float f;
    asm("cvt.f32.f16 %0, %1;" : "=f"(f) : "h"(h));
    return f;
}
__device__ __forceinline__ void mma_f16(float* c,
                                        uint32_t a0, uint32_t a1, uint32_t a2, uint32_t a3,
                                        uint32_t b0, uint32_t b1) {
    asm volatile(
        "mma.sync.aligned.m16n8k16.row.col.f32.f16.f16.f32 "
        "{%0,%1,%2,%3}, {%4,%5,%6,%7}, {%8,%9}, {%0,%1,%2,%3};"
        : "+f"(c[0]), "+f"(c[1]), "+f"(c[2]), "+f"(c[3])
        : "r"(a0), "r"(a1), "r"(a2), "r"(a3), "r"(b0), "r"(b1));
}

extern __shared__ float smem[];

// ================== Prep: split weights into fp16 hi/lo, fragment order ==================
// one thread per 32-bit output word
__global__ __launch_bounds__(256, 4)
void split_kernel(const float* __restrict__ W_in,
                  const float* __restrict__ W1,
                  const float* __restrict__ W2,
                  const float* __restrict__ W3,
                  const float* __restrict__ W4)
{
    int i = blockIdx.x * 256 + threadIdx.x;
    if (i >= TOT_WORDS) return;

    const float* src;
    int K, kt, mt, r, lane;
    if (i < WIN_WORDS) {
        int j = i;
        r    = j & 3;
        lane = (j >> 2) & 31;
        int rest = j >> 7;
        kt = rest % 49;
        mt = rest / 49;
        K  = 784;
        src = W_in;
    } else {
        int j   = i - WIN_WORDS;
        int blk = j >> 13;           // 8192 words per block
        int jj  = j & (WBLK_WORDS - 1);
        r    = jj & 3;
        lane = (jj >> 2) & 31;
        int rest = jj >> 7;
        kt = rest & 7;
        mt = rest >> 3;
        K  = 128;
        src = (blk == 0 ? W1 : blk == 1 ? W2 : blk == 2 ? W3 : W4);
    }
    int g = lane >> 2;
    int t = lane & 3;
    int m  = mt * 16 + g + ((r & 1) << 3);
    int kk = kt * 16 + ((r >> 1) << 3) + 2 * t;

    float v0 = src[m * K + kk];
    float v1 = src[m * K + kk + 1];
    uint32_t h = hpack(v0, v1);
    float2 hr = hunpack(h);
    uint32_t l = hpack(v0 - hr.x, v1 - hr.y);
    g_whw[i] = h;
    g_wlw[i] = l;
}

// ================== Main: phase0 + 4 implicit blocks + softmax ==================
// grid 256 CTAs x 8 rows, 256 threads (8 warps; warp = one 16-unit M-tile)
__global__ __launch_bounds__(NTHREADS, 2)
void blocks_kernel(const float* __restrict__ x,
                   const float* __restrict__ b_in,
                   const float* __restrict__ W_out,
                   const float* __restrict__ b_out,
                   float* __restrict__ out)
{
    const int tid  = threadIdx.x;
    const int row0 = blockIdx.x * 8;

    char* smem_c = (char*)smem;
    const uint32_t sbase = smem_u32(smem);

    float* bufX = (float*)(smem_c + BUFX_BYTE);
    float* sEpi = (float*)(smem_c + EPI_BYTE);

    const int lane = tid & 31;
    const int warp = tid >> 5;     // = M-tile index (0..7)
    const int g    = lane >> 2;
    const int t    = lane & 3;

    const int      l0 = 8 * t + (g >> 1);
    const uint32_t hb = (uint32_t)(g & 1) * 2;

    const uint4* whp = (const uint4*)g_whw;
    const uint4* wlp = (const uint4*)g_wlw;

    // =========== Phase 0 (fused): xf = x @ W_in^T + b_in via HMMA (3-term) ===========
    float xf[4];
    {
        float p0[4], p1[4], p2[4];
        {
            int m = warp * 16 + g;
            float b0 = b_in[m], b1 = b_in[m + 8];
            p0[0] = b0;  p0[1] = b0;  p0[2] = b1;  p0[3] = b1;
            #pragma unroll
            for (int e = 0; e < 4; ++e) { p1[e] = 0.f; p2[e] = 0.f; }
        }
        const float* xp_base = x + (row0 + g) * 784 + 2 * t;
        const uint4* whw = whp + (warp * 49) * 32 + lane;
        const uint4* wlw = wlp + (warp * 49) * 32 + lane;
        #pragma unroll 7
        for (int kt = 0; kt < 49; ++kt) {
            const int k0 = kt * 16;
            float2 xv0 = *(const float2*)(xp_base + k0);
            float2 xv1 = *(const float2*)(xp_base + k0 + 8);
            uint32_t bh0 = hpack(xv0.x, xv0.y);
            uint32_t bh1 = hpack(xv1.x, xv1.y);
            float2 r0 = hunpack(bh0);
            float2 r1 = hunpack(bh1);
            uint32_t bl0 = hpack(xv0.x - r0.x, xv0.y - r0.y);
            uint32_t bl1 = hpack(xv1.x - r1.x, xv1.y - r1.y);
            uint4 ah = whw[kt * 32];
            uint4 al = wlw[kt * 32];
            mma_f16(p0, ah.x, ah.y, ah.z, ah.w, bh0, bh1);
            mma_f16(p1, ah.x, ah.y, ah.z, ah.w, bl0, bl1);
            mma_f16(p2, al.x, al.y, al.z, al.w, bh0, bh1);
        }
        #pragma unroll
        for (int e = 0; e < 4; ++e) xf[e] = p0[e] + (p1[e] + p2[e]);
    }

    // =========== 4 implicit blocks ===========
    uint32_t wh[8][4];
    float zv[4];

    for (int blk = 0; blk < 4; ++blk) {
        const uint4* whw = whp + BLK0_U4 + blk * (WBLK_WORDS / 4) + (warp * 8) * 32 + lane;
        const uint4* wlw = wlp + BLK0_U4 + blk * (WBLK_WORDS / 4) + (warp * 8) * 32 + lane;

        // ---- Wh fragments -> regs (8 x LDG.128) ----
        #pragma unroll
        for (int kt = 0; kt < 8; ++kt) {
            uint4 w = whw[kt * 32];
            wh[kt][0] = w.x;  wh[kt][1] = w.y;  wh[kt][2] = w.z;  wh[kt][3] = w.w;
        }

        // ---- z0 = tanh(x) -> ZB buffer 0 (hi only) ----
        #pragma unroll
        for (int e = 0; e < 4; ++e) zv[e] = fast_tanh(xf[e]);

        {
            uint32_t base = (uint32_t)(warp * 256);
            #pragma unroll
            for (int e = 0; e < 4; ++e) {
                unsigned short h = f2h(zv[e]);
                uint32_t off = base + (uint32_t)(((e & 1) ? l0 + 4 : l0) * 8)
                             + (uint32_t)((e >> 1) * 4) + hb;
                asm volatile("st.shared.b16 [%0], %1;" :: "r"(sbase + ZBH0_BYTE + off), "h"(h) : "memory");
            }
        }
        __syncthreads();

        // ---- Picard iterations: cheap (Wh*zh) then full (3-term), ping-pong ZB ----
        for (int it = 0; it < N_ITER; ++it) {
            const bool cheap = (it < N_CHEAP);
            const uint32_t rb = (it & 1) ? 4096u : 0u;
            const uint32_t wb = (it & 1) ? 0u : 4096u;
            float a_hh[4], a_hl[4], a_lh[4];
            #pragma unroll
            for (int e = 0; e < 4; ++e) {
                a_hh[e] = xf[e];  a_hl[e] = 0.f;  a_lh[e] = 0.f;
            }

            if (cheap) {
                #pragma unroll
                for (int kt = 0; kt < 8; ++kt) {
                    uint32_t zh0, zh1;
                    uint32_t off = (uint32_t)((kt * 32 + lane) * 8);
                    asm volatile("ld.shared.v2.b32 {%0,%1}, [%2];"
                                 : "=r"(zh0), "=r"(zh1) : "r"(sbase + ZBH0_BYTE + rb + off));
                    mma_f16(a_hh, wh[kt][0], wh[kt][1], wh[kt][2], wh[kt][3], zh0, zh1);
                }
                #pragma unroll
                for (int e = 0; e < 4; ++e) zv[e] = fast_tanh(a_hh[e]);
            } else {
                #pragma unroll
                for (int kt = 0; kt < 8; ++kt) {
                    uint32_t zh0, zh1, zl0, zl1;
                    uint32_t off = (uint32_t)((kt * 32 + lane) * 8);
                    asm volatile("ld.shared.v2.b32 {%0,%1}, [%2];"
                                 : "=r"(zh0), "=r"(zh1) : "r"(sbase + ZBH0_BYTE + rb + off));
                    asm volatile("ld.shared.v2.b32 {%0,%1}, [%2];"
                                 : "=r"(zl0), "=r"(zl1) : "r"(sbase + ZBL0_BYTE + rb + off));
                    uint4 wl = wlw[kt * 32];   // Wl fragment straight from L2
                    mma_f16(a_hh, wh[kt][0], wh[kt][1], wh[kt][2], wh[kt][3], zh0, zh1);
                    mma_f16(a_hl, wh[kt][0], wh[kt][1], wh[kt][2], wh[kt][3], zl0, zl1);
                    mma_f16(a_lh, wl.x, wl.y, wl.z, wl.w, zh0, zh1);
                }
                #pragma unroll
                for (int e = 0; e < 4; ++e)
                    zv[e] = fast_tanh(a_hh[e] + (a_hl[e] + a_lh[e]));
            }

            if (it < N_ITER - 1) {
                const bool need_lo = (it >= N_CHEAP - 1);   // next iter is full
                uint32_t base = (uint32_t)(warp * 256);
                #pragma unroll
                for (int e = 0; e < 4; ++e) {
                    float zz = zv[e];
                    unsigned short h = f2h(zz);
                    uint32_t off = base + (uint32_t)(((e & 1) ? l0 + 4 : l0) * 8)
                                 + (uint32_t)((e >> 1) * 4) + hb;
                    asm volatile("st.shared.b16 [%0], %1;"
                                 :: "r"(sbase + ZBH0_BYTE + wb + off), "h"(h) : "memory");
                    if (need_lo) {
                        unsigned short l = f2h(zz - h2f(h));
                        asm volatile("st.shared.b16 [%0], %1;"
                                     :: "r"(sbase + ZBL0_BYTE + wb + off), "h"(l) : "memory");
                    }
                }
                __syncthreads();
            }
        }

        #pragma unroll
        for (int e = 0; e < 4; ++e) xf[e] = zv[e];
        __syncthreads();   // all ZB reads done before next block's z0 store
    }

    // ---- final z -> bufX ----
    {
        int m0 = warp * 16 + g;
        int n0 = 2 * t;
        *(float2*)&bufX[m0 * BXS + n0]       = make_float2(zv[0], zv[1]);
        *(float2*)&bufX[(m0 + 8) * BXS + n0] = make_float2(zv[2], zv[3]);
    }
    __syncthreads();

    // ---- epilogue: logits + softmax (8 rows) ----
    for (int idx = tid; idx < 10 * UNITS; idx += NTHREADS) sEpi[idx] = W_out[idx];
    if (tid < 10) sEpi[1280 + tid] = b_out[tid];
    __syncthreads();
    float* slog = sEpi + 1296;   // [o][r], 80 floats
    if (tid < 80) {
        int o = tid >> 3;
        int r = tid & 7;
        float acc = sEpi[1280 + o];
        #pragma unroll 8
        for (int k = 0; k < UNITS; ++k)
            acc += bufX[k * BXS + r] * sEpi[o * UNITS + k];
        slog[o * 8 + r] = acc;
    }
    __syncthreads();
    if (tid < 8) {
        int r = tid;
        float l[10];
        float m = -INFINITY;
        #pragma unroll
        for (int o = 0; o < 10; ++o) { l[o] = slog[o * 8 + r]; m = fmaxf(m, l[o]); }
        float s = 0.f;
        #pragma unroll
        for (int o = 0; o < 10; ++o) { l[o] = expf(l[o] - m); s += l[o]; }
        float inv = 1.f / s;
        #pragma unroll
        for (int o = 0; o < 10; ++o) out[(row0 + r) * 10 + o] = l[o] * inv;
    }
}

extern "C" void kernel_launch(void* const* d_in, const int* in_sizes, int n_in,
                              void* d_out, int out_size)
{
    const float* x     = (const float*)d_in[0];
    const float* W_in  = (const float*)d_in[1];
    const float* b_in  = (const float*)d_in[2];
    const float* W1    = (const float*)d_in[3];
    const float* W2    = (const float*)d_in[4];
    const float* W3    = (const float*)d_in[5];
    const float* W4    = (const float*)d_in[6];
    const float* W_out = (const float*)d_in[7];
    const float* b_out = (const float*)d_in[8];
    float* out = (float*)d_out;

    cudaFuncSetAttribute(blocks_kernel,
                         cudaFuncAttributeMaxDynamicSharedMemorySize, K2_SMEM_BYTES);

    split_kernel<<<(TOT_WORDS + 255) / 256, 256>>>(W_in, W1, W2, W3, W4);
    blocks_kernel<<<256, NTHREADS, K2_SMEM_BYTES>>>(x, b_in, W_out, b_out, out);
}

// round 13
// speedup vs baseline: 2.2770x; 1.0564x over previous
#include <cuda_runtime.h>
#include <math.h>
#include <stdint.h>

#define UNITS     128
#define N_ITER    8
#define N_CHEAP   6      // iterations 0..N_CHEAP-1 use Wh*zh only
#define BXS       10
#define NTHREADS  256

// ---- blocks_kernel smem (bytes) ----
#define BUFX_BYTE  0         // 128*10*4 = 5120
#define ZBH0_BYTE  5120
#define ZBL0_BYTE  7168
#define ZBH1_BYTE  9216
#define ZBL1_BYTE  11264
#define EPI_BYTE   13312     // 1376 floats = 5504 B
#define K2_SMEM_BYTES 18816

// fragment-ordered fp16 weights, 32-bit words:
// W_in: [mt(8)][kt(49)][lane(32)][r(4)] = 50176 words
// W1..4: [blk(4)][mt(8)][kt(8)][lane(32)][r(4)] = 4*8192 words
#define WIN_WORDS  50176
#define WBLK_WORDS 8192
#define TOT_WORDS  (WIN_WORDS + 4 * WBLK_WORDS)
#define BLK0_U4    (WIN_WORDS / 4)
__device__ uint32_t g_whw[TOT_WORDS];
__device__ uint32_t g_wlw[TOT_WORDS];

// fragment-ordered fp16 x (B-fragments): [rowblk(256)][kt(49)][lane(32)] of uint2
#define XFRAG_N (256 * 49 * 32)
__device__ uint2 g_xh[XFRAG_N];
__device__ uint2 g_xl[XFRAG_N];

__device__ __forceinline__ uint32_t smem_u32(const void* p) {
    uint32_t a;
    asm("{ .reg .u64 t; cvta.to.shared.u64 t, %1; cvt.u32.u64 %0, t; }" : "=r"(a) : "l"(p));
    return a;
}
// accurate tanh (rel err ~1e-6): used in full iterations (incl. final)
__device__ __forceinline__ float fast_tanh(float x) {
    float e, r;
    asm("ex2.approx.f32 %0, %1;" : "=f"(e) : "f"(x * 2.8853900817779268f));
    asm("rcp.approx.f32 %0, %1;" : "=f"(r) : "f"(e + 1.0f));
    return fmaf(-2.0f, r, 1.0f);
}
// HW tanh (MUFU.TANH, 1 instr, rel err ~5e-4): cheap iterations only
__device__ __forceinline__ float hw_tanh(float x) {
    float y;
    asm("tanh.approx.f32 %0, %1;" : "=f"(y) : "f"(x));
    return y;
}
__device__ __forceinline__ uint32_t hpack(float lo, float hi) {
    uint32_t r;
    asm("cvt.rn.f16x2.f32 %0, %1, %2;" : "=r"(r) : "f"(hi), "f"(lo));
    return r;
}
__device__ __forceinline__ float2 hunpack(uint32_t p) {
    float2 f;
    asm("{ .reg .b16 l, h; mov.b32 {l, h}, %2; cvt.f32.f16 %0, l; cvt.f32.f16 %1, h; }"
        : "=f"(f.x), "=f"(f.y) : "r"(p));
    return f;
}
__device__ __forceinline__ unsigned short f2h(float f) {
    unsigned short h;
    asm("cvt.rn.f16.f32 %0, %1;" : "=h"(h) : "f"(f));
    return h;
}
__device__ __forceinline__ float h2f(unsigned short h) {
    float f;
    asm("cvt.f32.f16 %0, %1;" : "=f"(f) : "h"(h));
    return f;
}
__device__ __forceinline__ void mma_f16(float* c,
                                        uint32_t a0, uint32_t a1, uint32_t a2, uint32_t a3,
                                        uint32_t b0, uint32_t b1) {
    asm volatile(
        "mma.sync.aligned.m16n8k16.row.col.f32.f16.f16.f32 "
        "{%0,%1,%2,%3}, {%4,%5,%6,%7}, {%8,%9}, {%0,%1,%2,%3};"
        : "+f"(c[0]), "+f"(c[1]), "+f"(c[2]), "+f"(c[3])
        : "r"(a0), "r"(a1), "r"(a2), "r"(a3), "r"(b0), "r"(b1));
}

extern __shared__ float smem[];

// ================== Prep 1: split weights into fp16 hi/lo, fragment order ==================
__global__ __launch_bounds__(256, 4)
void split_kernel(const float* __restrict__ W_in,
                  const float* __restrict__ W1,
                  const float* __restrict__ W2,
                  const float* __restrict__ W3,
                  const float* __restrict__ W4)
{
    int i = blockIdx.x * 256 + threadIdx.x;
    if (i >= TOT_WORDS) return;

    const float* src;
    int K, kt, mt, r, lane;
    if (i < WIN_WORDS) {
        int j = i;
        r    = j & 3;
        lane = (j >> 2) & 31;
        int rest = j >> 7;
        kt = rest % 49;
        mt = rest / 49;
        K  = 784;
        src = W_in;
    } else {
        int j   = i - WIN_WORDS;
        int blk = j >> 13;
        int jj  = j & (WBLK_WORDS - 1);
        r    = jj & 3;
        lane = (jj >> 2) & 31;
        int rest = jj >> 7;
        kt = rest & 7;
        mt = rest >> 3;
        K  = 128;
        src = (blk == 0 ? W1 : blk == 1 ? W2 : blk == 2 ? W3 : W4);
    }
    int g = lane >> 2;
    int t = lane & 3;
    int m  = mt * 16 + g + ((r & 1) << 3);
    int kk = kt * 16 + ((r >> 1) << 3) + 2 * t;

    float v0 = src[m * K + kk];
    float v1 = src[m * K + kk + 1];
    uint32_t h = hpack(v0, v1);
    float2 hr = hunpack(h);
    uint32_t l = hpack(v0 - hr.x, v1 - hr.y);
    g_whw[i] = h;
    g_wlw[i] = l;
}

// ================== Prep 2: split x into fp16 hi/lo B-fragments ==================
__global__ __launch_bounds__(256, 4)
void xsplit_kernel(const float* __restrict__ x)
{
    int i = blockIdx.x * 256 + threadIdx.x;   // i = (rowblk*49 + kt)*32 + lane
    if (i >= XFRAG_N) return;
    int lane   = i & 31;
    int kt     = (i >> 5) % 49;
    int rowblk = (i >> 5) / 49;
    int g = lane >> 2;
    int t = lane & 3;
    const float* xp = x + (rowblk * 8 + g) * 784 + kt * 16 + 2 * t;
    float2 v0 = *(const float2*)xp;
    float2 v1 = *(const float2*)(xp + 8);
    uint32_t h0 = hpack(v0.x, v0.y);
    uint32_t h1 = hpack(v1.x, v1.y);
    float2 r0 = hunpack(h0);
    float2 r1 = hunpack(h1);
    uint32_t l0 = hpack(v0.x - r0.x, v0.y - r0.y);
    uint32_t l1 = hpack(v1.x - r1.x, v1.y - r1.y);
    g_xh[i] = make_uint2(h0, h1);
    g_xl[i] = make_uint2(l0, l1);
}

// ================== Main: phase0 + 4 implicit blocks + softmax ==================
// grid 256 CTAs x 8 rows, 256 threads (8 warps; warp = one 16-unit M-tile)
__global__ __launch_bounds__(NTHREADS, 2)
void blocks_kernel(const float* __restrict__ b_in,
                   const float* __restrict__ W_out,
                   const float* __restrict__ b_out,
                   float* __restrict__ out)
{
    const int tid  = threadIdx.x;
    const int row0 = blockIdx.x * 8;

    char* smem_c = (char*)smem;
    const uint32_t sbase = smem_u32(smem);

    float* bufX = (float*)(smem_c + BUFX_BYTE);
    float* sEpi = (float*)(smem_c + EPI_BYTE);

    const int lane = tid & 31;
    const int warp = tid >> 5;     // = M-tile index (0..7)
    const int g    = lane >> 2;
    const int t    = lane & 3;

    const int      l0 = 8 * t + (g >> 1);
    const uint32_t hb = (uint32_t)(g & 1) * 2;

    const uint4* whp = (const uint4*)g_whw;
    const uint4* wlp = (const uint4*)g_wlw;

    // =========== Phase 0 (fused): xf = x @ W_in^T + b_in via HMMA (3-term) ===========
    float xf[4];
    {
        float p0[4], p1[4], p2[4];
        {
            int m = warp * 16 + g;
            float b0 = b_in[m], b1 = b_in[m + 8];
            p0[0] = b0;  p0[1] = b0;  p0[2] = b1;  p0[3] = b1;
            #pragma unroll
            for (int e = 0; e < 4; ++e) { p1[e] = 0.f; p2[e] = 0.f; }
        }
        const uint4* whw = whp + (warp * 49) * 32 + lane;
        const uint4* wlw = wlp + (warp * 49) * 32 + lane;
        const uint2* xhw = g_xh + (blockIdx.x * 49) * 32 + lane;
        const uint2* xlw = g_xl + (blockIdx.x * 49) * 32 + lane;
        #pragma unroll 7
        for (int kt = 0; kt < 49; ++kt) {
            uint2 bh = xhw[kt * 32];
            uint2 bl = xlw[kt * 32];
            uint4 ah = whw[kt * 32];
            uint4 al = wlw[kt * 32];
            mma_f16(p0, ah.x, ah.y, ah.z, ah.w, bh.x, bh.y);
            mma_f16(p1, ah.x, ah.y, ah.z, ah.w, bl.x, bl.y);
            mma_f16(p2, al.x, al.y, al.z, al.w, bh.x, bh.y);
        }
        #pragma unroll
        for (int e = 0; e < 4; ++e) xf[e] = p0[e] + (p1[e] + p2[e]);
    }

    // =========== 4 implicit blocks ===========
    uint32_t wh[8][4];
    float zv[4];

    for (int blk = 0; blk < 4; ++blk) {
        const uint4* whw = whp + BLK0_U4 + blk * (WBLK_WORDS / 4) + (warp * 8) * 32 + lane;
        const uint4* wlw = wlp + BLK0_U4 + blk * (WBLK_WORDS / 4) + (warp * 8) * 32 + lane;

        // ---- Wh fragments -> regs (8 x LDG.128) ----
        #pragma unroll
        for (int kt = 0; kt < 8; ++kt) {
            uint4 w = whw[kt * 32];
            wh[kt][0] = w.x;  wh[kt][1] = w.y;  wh[kt][2] = w.z;  wh[kt][3] = w.w;
        }

        // ---- z0 = tanh(x) -> ZB buffer 0 (hi only) ----
        #pragma unroll
        for (int e = 0; e < 4; ++e) zv[e] = hw_tanh(xf[e]);

        {
            uint32_t base = (uint32_t)(warp * 256);
            #pragma unroll
            for (int e = 0; e < 4; ++e) {
                unsigned short h = f2h(zv[e]);
                uint32_t off = base + (uint32_t)(((e & 1) ? l0 + 4 : l0) * 8)
                             + (uint32_t)((e >> 1) * 4) + hb;
                asm volatile("st.shared.b16 [%0], %1;" :: "r"(sbase + ZBH0_BYTE + off), "h"(h) : "memory");
            }
        }
        __syncthreads();

        // ---- Picard iterations: cheap (Wh*zh) then full (3-term), ping-pong ZB ----
        for (int it = 0; it < N_ITER; ++it) {
            const bool cheap = (it < N_CHEAP);
            const uint32_t rb = (it & 1) ? 4096u : 0u;
            const uint32_t wb = (it & 1) ? 0u : 4096u;
            float a_hh[4], a_hl[4], a_lh[4];
            #pragma unroll
            for (int e = 0; e < 4; ++e) {
                a_hh[e] = xf[e];  a_hl[e] = 0.f;  a_lh[e] = 0.f;
            }

            if (cheap) {
                #pragma unroll
                for (int kt = 0; kt < 8; ++kt) {
                    uint32_t zh0, zh1;
                    uint32_t off = (uint32_t)((kt * 32 + lane) * 8);
                    asm volatile("ld.shared.v2.b32 {%0,%1}, [%2];"
                                 : "=r"(zh0), "=r"(zh1) : "r"(sbase + ZBH0_BYTE + rb + off));
                    mma_f16(a_hh, wh[kt][0], wh[kt][1], wh[kt][2], wh[kt][3], zh0, zh1);
                }
                #pragma unroll
                for (int e = 0; e < 4; ++e) zv[e] = hw_tanh(a_hh[e]);
            } else {
                #pragma unroll
                for (int kt = 0; kt < 8; ++kt) {
                    uint32_t zh0, zh1, zl0, zl1;
                    uint32_t off = (uint32_t)((kt * 32 + lane) * 8);
                    asm volatile("ld.shared.v2.b32 {%0,%1}, [%2];"
                                 : "=r"(zh0), "=r"(zh1) : "r"(sbase + ZBH0_BYTE + rb + off));
                    asm volatile("ld.shared.v2.b32 {%0,%1}, [%2];"
                                 : "=r"(zl0), "=r"(zl1) : "r"(sbase + ZBL0_BYTE + rb + off));
                    uint4 wl = wlw[kt * 32];   // Wl fragment straight from L2
                    mma_f16(a_hh, wh[kt][0], wh[kt][1], wh[kt][2], wh[kt][3], zh0, zh1);
                    mma_f16(a_hl, wh[kt][0], wh[kt][1], wh[kt][2], wh[kt][3], zl0, zl1);
                    mma_f16(a_lh, wl.x, wl.y, wl.z, wl.w, zh0, zh1);
                }
                #pragma unroll
                for (int e = 0; e < 4; ++e)
                    zv[e] = fast_tanh(a_hh[e] + (a_hl[e] + a_lh[e]));
            }

            if (it < N_ITER - 1) {
                const bool need_lo = (it >= N_CHEAP - 1);   // next iter is full
                uint32_t base = (uint32_t)(warp * 256);
                #pragma unroll
                for (int e = 0; e < 4; ++e) {
                    float zz = zv[e];
                    unsigned short h = f2h(zz);
                    uint32_t off = base + (uint32_t)(((e & 1) ? l0 + 4 : l0) * 8)
                                 + (uint32_t)((e >> 1) * 4) + hb;
                    asm volatile("st.shared.b16 [%0], %1;"
                                 :: "r"(sbase + ZBH0_BYTE + wb + off), "h"(h) : "memory");
                    if (need_lo) {
                        unsigned short l = f2h(zz - h2f(h));
                        asm volatile("st.shared.b16 [%0], %1;"
                                     :: "r"(sbase + ZBL0_BYTE + wb + off), "h"(l) : "memory");
                    }
                }
                __syncthreads();
            }
        }

        #pragma unroll
        for (int e = 0; e < 4; ++e) xf[e] = zv[e];
        __syncthreads();   // all ZB reads done before next block's z0 store
    }

    // ---- final z -> bufX ----
    {
        int m0 = warp * 16 + g;
        int n0 = 2 * t;
        *(float2*)&bufX[m0 * BXS + n0]       = make_float2(zv[0], zv[1]);
        *(float2*)&bufX[(m0 + 8) * BXS + n0] = make_float2(zv[2], zv[3]);
    }
    __syncthreads();

    // ---- epilogue: logits + softmax (8 rows) ----
    for (int idx = tid; idx < 10 * UNITS; idx += NTHREADS) sEpi[idx] = W_out[idx];
    if (tid < 10) sEpi[1280 + tid] = b_out[tid];
    __syncthreads();
    float* slog = sEpi + 1296;   // [o][r], 80 floats
    if (tid < 80) {
        int o = tid >> 3;
        int r = tid & 7;
        float acc = sEpi[1280 + o];
        #pragma unroll 8
        for (int k = 0; k < UNITS; ++k)
            acc += bufX[k * BXS + r] * sEpi[o * UNITS + k];
        slog[o * 8 + r] = acc;
    }
    __syncthreads();
    if (tid < 8) {
        int r = tid;
        float l[10];
        float m = -INFINITY;
        #pragma unroll
        for (int o = 0; o < 10; ++o) { l[o] = slog[o * 8 + r]; m = fmaxf(m, l[o]); }
        float s = 0.f;
        #pragma unroll
        for (int o = 0; o < 10; ++o) { l[o] = expf(l[o] - m); s += l[o]; }
        float inv = 1.f / s;
        #pragma unroll
        for (int o = 0; o < 10; ++o) out[(row0 + r) * 10 + o] = l[o] * inv;
    }
}

extern "C" void kernel_launch(void* const* d_in, const int* in_sizes, int n_in,
                              void* d_out, int out_size)
{
    const float* x     = (const float*)d_in[0];
    const float* W_in  = (const float*)d_in[1];
    const float* b_in  = (const float*)d_in[2];
    const float* W1    = (const float*)d_in[3];
    const float* W2    = (const float*)d_in[4];
    const float* W3    = (const float*)d_in[5];
    const float* W4    = (const float*)d_in[6];
    const float* W_out = (const float*)d_in[7];
    const float* b_out = (const float*)d_in[8];
    float* out = (float*)d_out;

    cudaFuncSetAttribute(blocks_kernel,
                         cudaFuncAttributeMaxDynamicSharedMemorySize, K2_SMEM_BYTES);

    split_kernel<<<(TOT_WORDS + 255) / 256, 256>>>(W_in, W1, W2, W3, W4);
    xsplit_kernel<<<(XFRAG_N + 255) / 256, 256>>>(x);
    blocks_kernel<<<256, NTHREADS, K2_SMEM_BYTES>>>(b_in, W_out, b_out, out);
}

// round 14
// speedup vs baseline: 2.6112x; 1.1468x over previous
#include <cuda_runtime.h>
#include <math.h>
#include <stdint.h>

#define UNITS     128
#define N_ITER    7
#define N_CHEAP   5      // iterations 0..N_CHEAP-1 use Wh*zh only
#define BXS       10
#define NTHREADS  256

// ---- blocks_kernel smem (bytes) ----
#define BUFX_BYTE  0         // 128*10*4 = 5120
#define ZBH0_BYTE  5120
#define ZBL0_BYTE  7168
#define ZBH1_BYTE  9216
#define ZBL1_BYTE  11264
#define EPI_BYTE   13312     // 1376 floats = 5504 B
#define K2_SMEM_BYTES 18816

// fragment-ordered fp16 weights, 32-bit words:
// W_in: [mt(8)][kt(49)][lane(32)][r(4)] = 50176 words
// W1..4: [blk(4)][mt(8)][kt(8)][lane(32)][r(4)] = 4*8192 words
#define WIN_WORDS  50176
#define WBLK_WORDS 8192
#define TOT_WORDS  (WIN_WORDS + 4 * WBLK_WORDS)
#define BLK0_U4    (WIN_WORDS / 4)
__device__ uint32_t g_whw[TOT_WORDS];
__device__ uint32_t g_wlw[TOT_WORDS];

// fragment-ordered fp16 x (B-fragments): [rowblk(256)][kt(49)][lane(32)] of uint2
#define XFRAG_N (256 * 49 * 32)
__device__ uint2 g_xh[XFRAG_N];
__device__ uint2 g_xl[XFRAG_N];

// fused prep: blocks [0, WPREP_BLOCKS) do weights, rest do x
#define WPREP_BLOCKS ((TOT_WORDS + 255) / 256)
#define XPREP_BLOCKS ((XFRAG_N + 255) / 256)
#define PREP_BLOCKS  (WPREP_BLOCKS + XPREP_BLOCKS)

__device__ __forceinline__ uint32_t smem_u32(const void* p) {
    uint32_t a;
    asm("{ .reg .u64 t; cvta.to.shared.u64 t, %1; cvt.u32.u64 %0, t; }" : "=r"(a) : "l"(p));
    return a;
}
// accurate tanh (rel err ~1e-6): used in full iterations (incl. final)
__device__ __forceinline__ float fast_tanh(float x) {
    float e, r;
    asm("ex2.approx.f32 %0, %1;" : "=f"(e) : "f"(x * 2.8853900817779268f));
    asm("rcp.approx.f32 %0, %1;" : "=f"(r) : "f"(e + 1.0f));
    return fmaf(-2.0f, r, 1.0f);
}
// HW tanh (MUFU.TANH, 1 instr, rel err ~5e-4): cheap iterations only
__device__ __forceinline__ float hw_tanh(float x) {
    float y;
    asm("tanh.approx.f32 %0, %1;" : "=f"(y) : "f"(x));
    return y;
}
__device__ __forceinline__ uint32_t hpack(float lo, float hi) {
    uint32_t r;
    asm("cvt.rn.f16x2.f32 %0, %1, %2;" : "=r"(r) : "f"(hi), "f"(lo));
    return r;
}
__device__ __forceinline__ float2 hunpack(uint32_t p) {
    float2 f;
    asm("{ .reg .b16 l, h; mov.b32 {l, h}, %2; cvt.f32.f16 %0, l; cvt.f32.f16 %1, h; }"
        : "=f"(f.x), "=f"(f.y) : "r"(p));
    return f;
}
__device__ __forceinline__ unsigned short f2h(float f) {
    unsigned short h;
    asm("cvt.rn.f16.f32 %0, %1;" : "=h"(h) : "f"(f));
    return h;
}
__device__ __forceinline__ float h2f(unsigned short h) {
    float f;
    asm("cvt.f32.f16 %0, %1;" : "=f"(f) : "h"(h));
    return f;
}
__device__ __forceinline__ void mma_f16(float* c,
                                        uint32_t a0, uint32_t a1, uint32_t a2, uint32_t a3,
                                        uint32_t b0, uint32_t b1) {
    asm volatile(
        "mma.sync.aligned.m16n8k16.row.col.f32.f16.f16.f32 "
        "{%0,%1,%2,%3}, {%4,%5,%6,%7}, {%8,%9}, {%0,%1,%2,%3};"
        : "+f"(c[0]), "+f"(c[1]), "+f"(c[2]), "+f"(c[3])
        : "r"(a0), "r"(a1), "r"(a2), "r"(a3), "r"(b0), "r"(b1));
}

extern __shared__ float smem[];

// ================== Fused prep: weights + x -> fp16 hi/lo fragment order ==================
__global__ __launch_bounds__(256, 4)
void prep_kernel(const float* __restrict__ W_in,
                 const float* __restrict__ W1,
                 const float* __restrict__ W2,
                 const float* __restrict__ W3,
                 const float* __restrict__ W4,
                 const float* __restrict__ x)
{
    if (blockIdx.x < WPREP_BLOCKS) {
        int i = blockIdx.x * 256 + threadIdx.x;
        if (i >= TOT_WORDS) return;

        const float* src;
        int K, kt, mt, r, lane;
        if (i < WIN_WORDS) {
            int j = i;
            r    = j & 3;
            lane = (j >> 2) & 31;
            int rest = j >> 7;
            kt = rest % 49;
            mt = rest / 49;
            K  = 784;
            src = W_in;
        } else {
            int j   = i - WIN_WORDS;
            int blk = j >> 13;
            int jj  = j & (WBLK_WORDS - 1);
            r    = jj & 3;
            lane = (jj >> 2) & 31;
            int rest = jj >> 7;
            kt = rest & 7;
            mt = rest >> 3;
            K  = 128;
            src = (blk == 0 ? W1 : blk == 1 ? W2 : blk == 2 ? W3 : W4);
        }
        int g = lane >> 2;
        int t = lane & 3;
        int m  = mt * 16 + g + ((r & 1) << 3);
        int kk = kt * 16 + ((r >> 1) << 3) + 2 * t;

        float v0 = src[m * K + kk];
        float v1 = src[m * K + kk + 1];
        uint32_t h = hpack(v0, v1);
        float2 hr = hunpack(h);
        uint32_t l = hpack(v0 - hr.x, v1 - hr.y);
        g_whw[i] = h;
        g_wlw[i] = l;
    } else {
        int i = (blockIdx.x - WPREP_BLOCKS) * 256 + threadIdx.x;
        if (i >= XFRAG_N) return;
        int lane   = i & 31;
        int kt     = (i >> 5) % 49;
        int rowblk = (i >> 5) / 49;
        int g = lane >> 2;
        int t = lane & 3;
        const float* xp = x + (rowblk * 8 + g) * 784 + kt * 16 + 2 * t;
        float2 v0 = *(const float2*)xp;
        float2 v1 = *(const float2*)(xp + 8);
        uint32_t h0 = hpack(v0.x, v0.y);
        uint32_t h1 = hpack(v1.x, v1.y);
        float2 r0 = hunpack(h0);
        float2 r1 = hunpack(h1);
        uint32_t l0 = hpack(v0.x - r0.x, v0.y - r0.y);
        uint32_t l1 = hpack(v1.x - r1.x, v1.y - r1.y);
        g_xh[i] = make_uint2(h0, h1);
        g_xl[i] = make_uint2(l0, l1);
    }
}

// ================== Main: phase0 + 4 implicit blocks + softmax ==================
// grid 256 CTAs x 8 rows, 256 threads (8 warps; warp = one 16-unit M-tile)
__global__ __launch_bounds__(NTHREADS, 2)
void blocks_kernel(const float* __restrict__ b_in,
                   const float* __restrict__ W_out,
                   const float* __restrict__ b_out,
                   float* __restrict__ out)
{
    const int tid  = threadIdx.x;
    const int row0 = blockIdx.x * 8;

    char* smem_c = (char*)smem;
    const uint32_t sbase = smem_u32(smem);

    float* bufX = (float*)(smem_c + BUFX_BYTE);
    float* sEpi = (float*)(smem_c + EPI_BYTE);

    const int lane = tid & 31;
    const int warp = tid >> 5;     // = M-tile index (0..7)
    const int g    = lane >> 2;
    const int t    = lane & 3;

    const int      l0 = 8 * t + (g >> 1);
    const uint32_t hb = (uint32_t)(g & 1) * 2;

    const uint4* whp = (const uint4*)g_whw;
    const uint4* wlp = (const uint4*)g_wlw;

    // =========== Phase 0 (fused): xf = x @ W_in^T + b_in via HMMA (3-term) ===========
    float xf[4];
    {
        float p0[4], p1[4], p2[4];
        {
            int m = warp * 16 + g;
            float b0 = b_in[m], b1 = b_in[m + 8];
            p0[0] = b0;  p0[1] = b0;  p0[2] = b1;  p0[3] = b1;
            #pragma unroll
            for (int e = 0; e < 4; ++e) { p1[e] = 0.f; p2[e] = 0.f; }
        }
        const uint4* whw = whp + (warp * 49) * 32 + lane;
        const uint4* wlw = wlp + (warp * 49) * 32 + lane;
        const uint2* xhw = g_xh + (blockIdx.x * 49) * 32 + lane;
        const uint2* xlw = g_xl + (blockIdx.x * 49) * 32 + lane;
        #pragma unroll 7
        for (int kt = 0; kt < 49; ++kt) {
            uint2 bh = xhw[kt * 32];
            uint2 bl = xlw[kt * 32];
            uint4 ah = whw[kt * 32];
            uint4 al = wlw[kt * 32];
            mma_f16(p0, ah.x, ah.y, ah.z, ah.w, bh.x, bh.y);
            mma_f16(p1, ah.x, ah.y, ah.z, ah.w, bl.x, bl.y);
            mma_f16(p2, al.x, al.y, al.z, al.w, bh.x, bh.y);
        }
        #pragma unroll
        for (int e = 0; e < 4; ++e) xf[e] = p0[e] + (p1[e] + p2[e]);
    }

    // =========== 4 implicit blocks ===========
    uint32_t wh[8][4];
    float zv[4];

    for (int blk = 0; blk < 4; ++blk) {
        const uint4* whw = whp + BLK0_U4 + blk * (WBLK_WORDS / 4) + (warp * 8) * 32 + lane;
        const uint4* wlw = wlp + BLK0_U4 + blk * (WBLK_WORDS / 4) + (warp * 8) * 32 + lane;

        // ---- Wh fragments -> regs (8 x LDG.128) ----
        #pragma unroll
        for (int kt = 0; kt < 8; ++kt) {
            uint4 w = whw[kt * 32];
            wh[kt][0] = w.x;  wh[kt][1] = w.y;  wh[kt][2] = w.z;  wh[kt][3] = w.w;
        }

        // ---- z0 = tanh(x) -> ZB buffer 0 (hi only) ----
        #pragma unroll
        for (int e = 0; e < 4; ++e) zv[e] = hw_tanh(xf[e]);

        {
            uint32_t base = (uint32_t)(warp * 256);
            #pragma unroll
            for (int e = 0; e < 4; ++e) {
                unsigned short h = f2h(zv[e]);
                uint32_t off = base + (uint32_t)(((e & 1) ? l0 + 4 : l0) * 8)
                             + (uint32_t)((e >> 1) * 4) + hb;
                asm volatile("st.shared.b16 [%0], %1;" :: "r"(sbase + ZBH0_BYTE + off), "h"(h) : "memory");
            }
        }
        __syncthreads();

        // ---- Picard iterations: cheap (Wh*zh) then full (3-term), ping-pong ZB ----
        for (int it = 0; it < N_ITER; ++it) {
            const bool cheap = (it < N_CHEAP);
            const uint32_t rb = (it & 1) ? 4096u : 0u;
            const uint32_t wb = (it & 1) ? 0u : 4096u;
            float a_hh[4], a_hl[4], a_lh[4];
            #pragma unroll
            for (int e = 0; e < 4; ++e) {
                a_hh[e] = xf[e];  a_hl[e] = 0.f;  a_lh[e] = 0.f;
            }

            if (cheap) {
                #pragma unroll
                for (int kt = 0; kt < 8; ++kt) {
                    uint32_t zh0, zh1;
                    uint32_t off = (uint32_t)((kt * 32 + lane) * 8);
                    asm volatile("ld.shared.v2.b32 {%0,%1}, [%2];"
                                 : "=r"(zh0), "=r"(zh1) : "r"(sbase + ZBH0_BYTE + rb + off));
                    mma_f16(a_hh, wh[kt][0], wh[kt][1], wh[kt][2], wh[kt][3], zh0, zh1);
                }
                #pragma unroll
                for (int e = 0; e < 4; ++e) zv[e] = hw_tanh(a_hh[e]);
            } else {
                #pragma unroll
                for (int kt = 0; kt < 8; ++kt) {
                    uint32_t zh0, zh1, zl0, zl1;
                    uint32_t off = (uint32_t)((kt * 32 + lane) * 8);
                    asm volatile("ld.shared.v2.b32 {%0,%1}, [%2];"
                                 : "=r"(zh0), "=r"(zh1) : "r"(sbase + ZBH0_BYTE + rb + off));
                    asm volatile("ld.shared.v2.b32 {%0,%1}, [%2];"
                                 : "=r"(zl0), "=r"(zl1) : "r"(sbase + ZBL0_BYTE + rb + off));
                    uint4 wl = wlw[kt * 32];   // Wl fragment straight from L2
                    mma_f16(a_hh, wh[kt][0], wh[kt][1], wh[kt][2], wh[kt][3], zh0, zh1);
                    mma_f16(a_hl, wh[kt][0], wh[kt][1], wh[kt][2], wh[kt][3], zl0, zl1);
                    mma_f16(a_lh, wl.x, wl.y, wl.z, wl.w, zh0, zh1);
                }
                #pragma unroll
                for (int e = 0; e < 4; ++e)
                    zv[e] = fast_tanh(a_hh[e] + (a_hl[e] + a_lh[e]));
            }

            if (it < N_ITER - 1) {
                const bool need_lo = (it >= N_CHEAP - 1);   // next iter is full
                uint32_t base = (uint32_t)(warp * 256);
                #pragma unroll
                for (int e = 0; e < 4; ++e) {
                    float zz = zv[e];
                    unsigned short h = f2h(zz);
                    uint32_t off = base + (uint32_t)(((e & 1) ? l0 + 4 : l0) * 8)
                                 + (uint32_t)((e >> 1) * 4) + hb;
                    asm volatile("st.shared.b16 [%0], %1;"
                                 :: "r"(sbase + ZBH0_BYTE + wb + off), "h"(h) : "memory");
                    if (need_lo) {
                        unsigned short l = f2h(zz - h2f(h));
                        asm volatile("st.shared.b16 [%0], %1;"
                                     :: "r"(sbase + ZBL0_BYTE + wb + off), "h"(l) : "memory");
                    }
                }
                __syncthreads();
            }
        }

        #pragma unroll
        for (int e = 0; e < 4; ++e) xf[e] = zv[e];
        __syncthreads();   // all ZB reads done before next block's z0 store
    }

    // ---- final z -> bufX ----
    {
        int m0 = warp * 16 + g;
        int n0 = 2 * t;
        *(float2*)&bufX[m0 * BXS + n0]       = make_float2(zv[0], zv[1]);
        *(float2*)&bufX[(m0 + 8) * BXS + n0] = make_float2(zv[2], zv[3]);
    }
    __syncthreads();

    // ---- epilogue: logits + softmax (8 rows) ----
    for (int idx = tid; idx < 10 * UNITS; idx += NTHREADS) sEpi[idx] = W_out[idx];
    if (tid < 10) sEpi[1280 + tid] = b_out[tid];
    __syncthreads();
    float* slog = sEpi + 1296;   // [o][r], 80 floats
    if (tid < 80) {
        int o = tid >> 3;
        int r = tid & 7;
        float acc = sEpi[1280 + o];
        #pragma unroll 8
        for (int k = 0; k < UNITS; ++k)
            acc += bufX[k * BXS + r] * sEpi[o * UNITS + k];
        slog[o * 8 + r] = acc;
    }
    __syncthreads();
    if (tid < 8) {
        int r = tid;
        float l[10];
        float m = -INFINITY;
        #pragma unroll
        for (int o = 0; o < 10; ++o) { l[o] = slog[o * 8 + r]; m = fmaxf(m, l[o]); }
        float s = 0.f;
        #pragma unroll
        for (int o = 0; o < 10; ++o) { l[o] = expf(l[o] - m); s += l[o]; }
        float inv = 1.f / s;
        #pragma unroll
        for (int o = 0; o < 10; ++o) out[(row0 + r) * 10 + o] = l[o] * inv;
    }
}

extern "C" void kernel_launch(void* const* d_in, const int* in_sizes, int n_in,
                              void* d_out, int out_size)
{
    const float* x     = (const float*)d_in[0];
    const float* W_in  = (const float*)d_in[1];
    const float* b_in  = (const float*)d_in[2];
    const float* W1    = (const float*)d_in[3];
    const float* W2    = (const float*)d_in[4];
    const float* W3    = (const float*)d_in[5];
    const float* W4    = (const float*)d_in[6];
    const float* W_out = (const float*)d_in[7];
    const float* b_out = (const float*)d_in[8];
    float* out = (float*)d_out;

    cudaFuncSetAttribute(blocks_kernel,
                         cudaFuncAttributeMaxDynamicSharedMemorySize, K2_SMEM_BYTES);

    prep_kernel<<<PREP_BLOCKS, 256>>>(W_in, W1, W2, W3, W4, x);
    blocks_kernel<<<256, NTHREADS, K2_SMEM_BYTES>>>(b_in, W_out, b_out, out);
}